// round 1
// baseline (speedup 1.0000x reference)
#include <cuda_runtime.h>
#include <math.h>
#include <math_constants.h>

#define T_LEN   8192
#define N_SC    16
#define TTILE   512
#define NTH     256
#define HALO    258                       // max wavelet half-width (256) + conv halo (2)
#define SXN     (TTILE + 2*HALO + 4)      // 1032 (+4 slack for sliding-window overread)
#define SW      520                       // smem row stride for [18][SW] planes
#define MAXW    3400                      // >= sum of wavelet lengths (3314)
#define NGR     129                       // (TTILE+4)/4 column groups per scale
#define C1COLS  514                       // conv1 output cols (c = 1..514)

// ---------------- wavelet tables (filled by init kernel each launch) ----------------
__device__ float2 g_wtab[MAXW];
__device__ int    g_len[N_SC];
__device__ int    g_off[N_SC];
__device__ int    g_tot;

__global__ void wav_init_kernel()
{
    const double la = log10(2.0);
    const double lb = log10(200.0);
    int Ls[N_SC], off[N_SC];
    int tot = 0;
    for (int i = 0; i < N_SC; ++i) {
        double e = (i == N_SC - 1) ? lb : la + (lb - la) * ((double)i / (double)(N_SC - 1));
        double s = pow(10.0, e);
        int L = (int)(6.0 * s);           // trunc, matches Python int()
        if (L > 512) L = 512;             // min(int(6s), 512)
        if ((L & 1) == 0) ++L;
        Ls[i] = L; off[i] = tot; tot += L;
    }
    if (tot > MAXW) tot = MAXW;           // safety clamp (should never trigger)
    if (threadIdx.x < N_SC) { g_len[threadIdx.x] = Ls[threadIdx.x]; g_off[threadIdx.x] = off[threadIdx.x]; }
    if (threadIdx.x == 0) g_tot = tot;

    for (int idx = threadIdx.x; idx < tot; idx += blockDim.x) {
        int s = 0;
        while (s < N_SC - 1 && idx >= off[s + 1]) ++s;
        int k = idx - off[s];
        double e  = (s == N_SC - 1) ? lb : la + (lb - la) * ((double)s / (double)(N_SC - 1));
        double sc = pow(10.0, e);
        int L = Ls[s];
        // t = linspace((-L)//2, L//2, L): lo = -(L+1)/2, hi = (L-1)/2, step = L/(L-1)
        double lo = -(double)((L + 1) / 2);
        double hi =  (double)(L / 2);
        double t  = (k == L - 1) ? hi : lo + (double)k * ((double)L / (double)(L - 1));
        double ts = t / sc;
        double nrm = 1.0 / (pow(CUDART_PI, 0.25) * sqrt(sc));
        double g = nrm * exp(-0.5 * ts * ts);
        g_wtab[idx] = make_float2((float)(g * cos(5.0 * ts)), (float)(g * sin(5.0 * ts)));
    }
}

// ---------------- fused CWT + correction-net + inverse kernel ----------------
__global__ __launch_bounds__(NTH, 2)
void wav_main_kernel(const float* __restrict__ x,
                     const float* __restrict__ w1,
                     const float* __restrict__ b1,
                     const float* __restrict__ w2,
                     const float* __restrict__ b2,
                     const float* __restrict__ blendl,
                     const float* __restrict__ lsc,
                     float* __restrict__ out)
{
    extern __shared__ float sm[];
    float*  sx  = sm;                       // SXN floats: x tile + reflect halo
    float2* swt = (float2*)(sm + SXN);      // MAXW float2: wavelet taps {wr, wi}
    float*  scw = sm + SXN + 2 * MAXW;      // [18][SW] raw CWT magnitudes, rows 0/17 zero-pad
    float*  sh1 = scw + 18 * SW;            // [18][SW] conv1+gelu output, rows 0/17 zero-pad
    float*  w1e = sh1 + 18 * SW;            // 144: w1[ch] folded with exp(log_scale_corr)
    float*  w2s = w1e + 144;                // 12 (9 used)
    int*    sLn = (int*)(w2s + 12);         // 16
    int*    sOf = sLn + 16;                 // 16

    const int tid = threadIdx.x;
    const int row = blockIdx.y;             // b*C + c
    const int ch  = row & 31;               // channel (C = 32)
    const int t0  = blockIdx.x * TTILE;
    const float* xr = x + (size_t)row * T_LEN;

    // ---- phase A: loads ----
    for (int i = tid; i < SXN; i += NTH) {
        int g = t0 - HALO + i;
        if (g < 0) g = -g;                          // reflect (no edge repeat)
        if (g >= T_LEN) g = 2 * (T_LEN - 1) - g;
        sx[i] = xr[g];
    }
    const int tot = g_tot;
    for (int i = tid; i < tot; i += NTH) swt[i] = g_wtab[i];
    for (int i = tid; i < SW; i += NTH) {           // zero the pad rows once
        scw[i] = 0.f; scw[17 * SW + i] = 0.f;
        sh1[i] = 0.f; sh1[17 * SW + i] = 0.f;
    }
    if (tid < N_SC) { sLn[tid] = g_len[tid]; sOf[tid] = g_off[tid]; }
    if (tid < 144) {
        // fold per-scale exp(log_scale_corrections) of the INPUT row into conv1 weights
        int s = tid / 9, r = tid - s * 9, ds = r / 3;
        int si = s + ds - 1; si = si < 0 ? 0 : (si > 15 ? 15 : si);  // clamped; padded rows are 0 anyway
        w1e[tid] = w1[ch * 9 + r] * expf(lsc[si]);
    }
    if (tid < 9) w2s[tid] = w2[ch * 9 + tid];
    __syncthreads();

    // ---- phase B: CWT magnitudes for cols c = 0..515 (t = t0-2+c), 16 scales ----
    // Each thread: 4 consecutive columns, sliding x-window in registers.
    for (int item = tid; item < N_SC * NGR; item += NTH) {
        int s  = item / NGR;
        int c0 = (item - s * NGR) * 4;
        int L  = sLn[s], p = L >> 1;
        const float2* wp = swt + sOf[s];
        int base = c0 + 256 - p;                    // sx index of x~[t(c0) - p]
        float xa = sx[base], xb = sx[base + 1], xc = sx[base + 2], xd = sx[base + 3];
        float cr0 = 0.f, cr1 = 0.f, cr2 = 0.f, cr3 = 0.f;
        float ci0 = 0.f, ci1 = 0.f, ci2 = 0.f, ci3 = 0.f;
        #pragma unroll 4
        for (int k = 0; k < L; ++k) {
            float2 w = wp[k];
            cr0 = fmaf(w.x, xa, cr0); ci0 = fmaf(w.y, xa, ci0);
            cr1 = fmaf(w.x, xb, cr1); ci1 = fmaf(w.y, xb, ci1);
            cr2 = fmaf(w.x, xc, cr2); ci2 = fmaf(w.y, xc, ci2);
            cr3 = fmaf(w.x, xd, cr3); ci3 = fmaf(w.y, xd, ci3);
            xa = xb; xb = xc; xc = xd; xd = sx[base + k + 4];
        }
        float* dst = scw + (s + 1) * SW + c0;
        int t = t0 - 2 + c0;
        dst[0] = ((unsigned)(t    ) < T_LEN) ? sqrtf(fmaf(cr0, cr0, ci0 * ci0)) : 0.f;
        dst[1] = ((unsigned)(t + 1) < T_LEN) ? sqrtf(fmaf(cr1, cr1, ci1 * ci1)) : 0.f;
        dst[2] = ((unsigned)(t + 2) < T_LEN) ? sqrtf(fmaf(cr2, cr2, ci2 * ci2)) : 0.f;
        dst[3] = ((unsigned)(t + 3) < T_LEN) ? sqrtf(fmaf(cr3, cr3, ci3 * ci3)) : 0.f;
    }
    __syncthreads();

    // ---- phase C: conv1 (scale-corrected input via folded weights) + exact GELU ----
    const float b1v = b1[ch];
    for (int item = tid; item < N_SC * C1COLS; item += NTH) {
        int s = item / C1COLS;
        int c = item - s * C1COLS + 1;              // 1..514
        const float* r0 = scw + s * SW + (c - 1);   // padded rows s..s+2
        const float* r1 = r0 + SW;
        const float* r2 = r1 + SW;
        const float* wv = w1e + s * 9;
        float v = b1v;
        v = fmaf(wv[0], r0[0], v); v = fmaf(wv[1], r0[1], v); v = fmaf(wv[2], r0[2], v);
        v = fmaf(wv[3], r1[0], v); v = fmaf(wv[4], r1[1], v); v = fmaf(wv[5], r1[2], v);
        v = fmaf(wv[6], r2[0], v); v = fmaf(wv[7], r2[1], v); v = fmaf(wv[8], r2[2], v);
        sh1[(s + 1) * SW + c] = 0.5f * v * (1.f + erff(v * 0.70710678118654752440f));
    }
    __syncthreads();

    // ---- phase D: conv2 + GELU + blend + ratio mean over scales + write out ----
    const float blend = 1.f / (1.f + expf(-blendl[0]));
    const float b2v = b2[ch];
    float wl[9];
    #pragma unroll
    for (int i = 0; i < 9; ++i) wl[i] = w2s[i];
    for (int c = 2 + tid; c < TTILE + 2; c += NTH) {
        float acc = 0.f;
        #pragma unroll 4
        for (int s = 1; s <= N_SC; ++s) {
            const float* r0 = sh1 + (s - 1) * SW + (c - 1);
            const float* r1 = r0 + SW;
            const float* r2 = r1 + SW;
            float v = b2v;
            v = fmaf(wl[0], r0[0], v); v = fmaf(wl[1], r0[1], v); v = fmaf(wl[2], r0[2], v);
            v = fmaf(wl[3], r1[0], v); v = fmaf(wl[4], r1[1], v); v = fmaf(wl[5], r1[2], v);
            v = fmaf(wl[6], r2[0], v); v = fmaf(wl[7], r2[1], v); v = fmaf(wl[8], r2[2], v);
            float h  = 0.5f * v * (1.f + erff(v * 0.70710678118654752440f));
            float cw = scw[s * SW + c];
            float bl = blend * h + (1.f - blend) * cw;
            acc += __fdividef(bl, cw + 1e-8f);
        }
        out[(size_t)row * T_LEN + (t0 + c - 2)] = sx[c + 256] * acc * (1.f / 16.f);
    }
}

extern "C" void kernel_launch(void* const* d_in, const int* in_sizes, int n_in,
                              void* d_out, int out_size)
{
    const float* x  = (const float*)d_in[0];
    const float* w1 = (const float*)d_in[1];
    const float* b1 = (const float*)d_in[2];
    const float* w2 = (const float*)d_in[3];
    const float* b2 = (const float*)d_in[4];
    const float* bl = (const float*)d_in[5];
    const float* ls = (const float*)d_in[6];
    float* out = (float*)d_out;

    const int rows = in_sizes[0] / T_LEN;   // B*C = 256

    const size_t smem = (size_t)(SXN + 2 * MAXW + 2 * 18 * SW + 144 + 12) * sizeof(float)
                        + 2 * 16 * sizeof(int);
    cudaFuncSetAttribute(wav_main_kernel, cudaFuncAttributeMaxDynamicSharedMemorySize, (int)smem);

    wav_init_kernel<<<1, 256>>>();
    dim3 grid(T_LEN / TTILE, rows);
    wav_main_kernel<<<grid, NTH, smem>>>(x, w1, b1, w2, b2, bl, ls, out);
}

// round 2
// speedup vs baseline: 1.3286x; 1.3286x over previous
#include <cuda_runtime.h>
#include <math.h>
#include <math_constants.h>

#define T_LEN   8192
#define N_SC    16
#define TTILE   512
#define NTH     256
#define HALO    258
#define SXN     1040                      // x tile + halo + slack, 16B-aligned count
#define SW      520                       // smem row stride for [18][SW] planes
#define MAXW    3408                      // >= sum of padded wavelet lengths (3368)
#define C1COLS  514                       // conv1 output cols (c = 1..514)

// ---------------- wavelet tables (filled by init kernel each launch) ----------------
__device__ float2 g_wtab[MAXW];           // padded: sh leading zeros, tail zeros to %4
__device__ int    g_Lp[N_SC];             // padded length (multiple of 4)
__device__ int    g_off[N_SC];            // padded offset (multiple of 4)
__device__ int    g_p[N_SC];              // half width L/2
__device__ int    g_sh[N_SC];             // leading zero taps
__device__ int    g_tot;

__global__ void wav_init_kernel()
{
    const double la = log10(2.0);
    const double lb = log10(200.0);
    int Ls[N_SC], Ps[N_SC], Sh[N_SC], Lp[N_SC], off[N_SC];
    int tot = 0;
    for (int i = 0; i < N_SC; ++i) {
        double e = (i == N_SC - 1) ? lb : la + (lb - la) * ((double)i / (double)(N_SC - 1));
        double s = pow(10.0, e);
        int L = (int)(6.0 * s);           // trunc, matches Python int()
        if (L > 512) L = 512;
        if ((L & 1) == 0) ++L;
        int p = L >> 1;
        int sh = ((2 - p) % 4 + 4) % 4;   // aligns x window start (cols start at cc=2)
        int lp = (L + sh + 3) & ~3;
        Ls[i] = L; Ps[i] = p; Sh[i] = sh; Lp[i] = lp; off[i] = tot; tot += lp;
    }
    if (threadIdx.x < N_SC) {
        g_Lp[threadIdx.x]  = Lp[threadIdx.x];
        g_off[threadIdx.x] = off[threadIdx.x];
        g_p[threadIdx.x]   = Ps[threadIdx.x];
        g_sh[threadIdx.x]  = Sh[threadIdx.x];
    }
    if (threadIdx.x == 0) g_tot = tot;

    for (int idx = threadIdx.x; idx < tot; idx += blockDim.x) {
        int s = 0;
        while (s < N_SC - 1 && idx >= off[s + 1]) ++s;
        int k = idx - off[s] - Sh[s];     // unpadded tap index
        int L = Ls[s];
        float2 v = make_float2(0.f, 0.f);
        if (k >= 0 && k < L) {
            double e  = (s == N_SC - 1) ? lb : la + (lb - la) * ((double)s / (double)(N_SC - 1));
            double sc = pow(10.0, e);
            double lo = -(double)((L + 1) / 2);
            double hi =  (double)(L / 2);
            double t  = (k == L - 1) ? hi : lo + (double)k * ((double)L / (double)(L - 1));
            double ts = t / sc;
            double nrm = 1.0 / (pow(CUDART_PI, 0.25) * sqrt(sc));
            double g = nrm * exp(-0.5 * ts * ts);
            v = make_float2((float)(g * cos(5.0 * ts)), (float)(g * sin(5.0 * ts)));
        }
        g_wtab[idx] = v;
    }
}

// ---------------- packed f32x2 helpers ----------------
__device__ __forceinline__ unsigned long long packdup(float v)
{
    unsigned long long r;
    unsigned u = __float_as_uint(v);
    asm("mov.b64 %0, {%1, %1};" : "=l"(r) : "r"(u));
    return r;
}
__device__ __forceinline__ void unpack2(unsigned long long a, float& lo, float& hi)
{
    unsigned ul, uh;
    asm("mov.b64 {%0, %1}, %2;" : "=r"(ul), "=r"(uh) : "l"(a));
    lo = __uint_as_float(ul); hi = __uint_as_float(uh);
}
#define FMA2(acc, w, xx) asm("fma.rn.f32x2 %0, %1, %2, %0;" : "+l"(acc) : "l"(w), "l"(xx))

// ---------------- fused CWT + correction-net + inverse kernel ----------------
__global__ __launch_bounds__(NTH, 2)
void wav_main_kernel(const float* __restrict__ x,
                     const float* __restrict__ w1,
                     const float* __restrict__ b1,
                     const float* __restrict__ w2,
                     const float* __restrict__ b2,
                     const float* __restrict__ blendl,
                     const float* __restrict__ lsc,
                     float* __restrict__ out)
{
    extern __shared__ float sm[];
    float*  sx  = sm;                       // SXN: x tile + reflect halo (16B aligned)
    float2* swt = (float2*)(sm + SXN);      // MAXW float2 padded wavelets
    float*  scw = sm + SXN + 2 * MAXW;      // [18][SW] CWT magnitudes, rows 0/17 zero
    float*  sh1 = scw + 18 * SW;            // [18][SW] conv1+gelu, rows 0/17 zero
    float*  w1e = sh1 + 18 * SW;            // 144 folded conv1 weights
    float*  w2s = w1e + 144;                // 12 (9 used)
    int*    sLp = (int*)(w2s + 12);         // 16
    int*    sOf = sLp + 16;                 // 16
    int*    sP  = sOf + 16;                 // 16
    int*    sSh = sP + 16;                  // 16

    const int tid  = threadIdx.x;
    const int wid  = tid >> 5;
    const int lane = tid & 31;
    const int row  = blockIdx.y;            // b*C + c
    const int ch   = row & 31;
    const int t0   = blockIdx.x * TTILE;
    const float* xr = x + (size_t)row * T_LEN;

    // ---- phase A: loads ----
    for (int i = tid; i < SXN; i += NTH) {
        int g = t0 - HALO + i;
        if (g < 0) g = -g;                          // reflect
        if (g >= T_LEN) g = 2 * (T_LEN - 1) - g;
        sx[i] = xr[g];
    }
    const int tot = g_tot;
    for (int i = tid; i < tot; i += NTH) swt[i] = g_wtab[i];
    for (int i = tid; i < SW; i += NTH) {
        scw[i] = 0.f; scw[17 * SW + i] = 0.f;
        sh1[i] = 0.f; sh1[17 * SW + i] = 0.f;
    }
    if (tid < N_SC) {
        sLp[tid] = g_Lp[tid]; sOf[tid] = g_off[tid];
        sP[tid]  = g_p[tid];  sSh[tid] = g_sh[tid];
    }
    if (tid < 144) {
        int s = tid / 9, r = tid - s * 9, ds = r / 3;
        int si = s + ds - 1; si = si < 0 ? 0 : (si > 15 ? 15 : si);
        w1e[tid] = w1[ch * 9 + r] * expf(lsc[si]);
    }
    if (tid < 9) w2s[tid] = w2[ch * 9 + tid];
    __syncthreads();

    // ---- phase B1: main CWT, cols 2..513, warp-uniform scale, packed f32x2 ----
    #pragma unroll 1
    for (int it = 0; it < 8; ++it) {
        int unit = wid + (it << 3);                 // 0..63
        int s = unit >> 2, q = unit & 3;
        int Lp = sLp[s];
        const ulonglong2* wp = (const ulonglong2*)swt + (sOf[s] >> 1);
        int c0 = 2 + (q << 7) + (lane << 2);        // 4 consecutive cols per lane
        int st = c0 + 256 - sP[s] - sSh[s];         // multiple of 4 by construction
        const float4* xv4 = (const float4*)(sx + st);
        float4 xa = xv4[0];
        unsigned long long q0 = packdup(xa.x), q1 = packdup(xa.y),
                           q2 = packdup(xa.z), q3 = packdup(xa.w);
        unsigned long long a0 = 0ull, a1 = 0ull, a2 = 0ull, a3 = 0ull;
        int nb = Lp >> 2;
        #pragma unroll 2
        for (int b = 1; b <= nb; ++b) {
            float4 xn = xv4[b];
            ulonglong2 wA = wp[0];
            ulonglong2 wB = wp[1];
            wp += 2;
            unsigned long long q4 = packdup(xn.x), q5 = packdup(xn.y),
                               q6 = packdup(xn.z), q7 = packdup(xn.w);
            FMA2(a0, wA.x, q0); FMA2(a1, wA.x, q1); FMA2(a2, wA.x, q2); FMA2(a3, wA.x, q3);
            FMA2(a0, wA.y, q1); FMA2(a1, wA.y, q2); FMA2(a2, wA.y, q3); FMA2(a3, wA.y, q4);
            FMA2(a0, wB.x, q2); FMA2(a1, wB.x, q3); FMA2(a2, wB.x, q4); FMA2(a3, wB.x, q5);
            FMA2(a0, wB.y, q3); FMA2(a1, wB.y, q4); FMA2(a2, wB.y, q5); FMA2(a3, wB.y, q6);
            q0 = q4; q1 = q5; q2 = q6; q3 = q7;
        }
        float* dst = scw + (s + 1) * SW + c0;
        float cr, ci;
        unpack2(a0, cr, ci); dst[0] = sqrtf(fmaf(cr, cr, ci * ci));
        unpack2(a1, cr, ci); dst[1] = sqrtf(fmaf(cr, cr, ci * ci));
        unpack2(a2, cr, ci); dst[2] = sqrtf(fmaf(cr, cr, ci * ci));
        unpack2(a3, cr, ci); dst[3] = sqrtf(fmaf(cr, cr, ci * ci));
    }

    // ---- phase B2: halo cols {0,1,514,515}, tap-split + shuffle reduce ----
    {
        const int hc0 = 0, hc1 = 1, hc2 = 514, hc3 = 515;
        #pragma unroll 1
        for (int it = 0; it < 8; ++it) {
            int task = wid + (it << 3);             // 0..63
            int s = task >> 2, h = task & 3;
            int cc = (h == 0) ? hc0 : (h == 1) ? hc1 : (h == 2) ? hc2 : hc3;
            int Lp = sLp[s];
            int stc = cc + 256 - sP[s] - sSh[s];
            const float2* wp = swt + sOf[s];
            float re = 0.f, im = 0.f;
            for (int k = lane; k < Lp; k += 32) {
                int ix = stc + k; ix = ix < 0 ? 0 : ix;   // clamped: weight is 0 there
                float xv = sx[ix];
                float2 w = wp[k];
                re = fmaf(w.x, xv, re); im = fmaf(w.y, xv, im);
            }
            #pragma unroll
            for (int o = 16; o; o >>= 1) {
                re += __shfl_down_sync(0xffffffffu, re, o);
                im += __shfl_down_sync(0xffffffffu, im, o);
            }
            if (lane == 0) {
                int t = t0 - 2 + cc;
                scw[(s + 1) * SW + cc] =
                    ((unsigned)t < T_LEN) ? sqrtf(fmaf(re, re, im * im)) : 0.f;
            }
        }
    }
    __syncthreads();

    // ---- phase C: conv1 (scale-corr folded into weights) + exact GELU ----
    const float b1v = b1[ch];
    for (int item = tid; item < N_SC * C1COLS; item += NTH) {
        int s = item / C1COLS;
        int c = item - s * C1COLS + 1;              // 1..514
        int t = t0 - 2 + c;
        const float* r0 = scw + s * SW + (c - 1);
        const float* r1 = r0 + SW;
        const float* r2 = r1 + SW;
        const float* wv = w1e + s * 9;
        float v = b1v;
        v = fmaf(wv[0], r0[0], v); v = fmaf(wv[1], r0[1], v); v = fmaf(wv[2], r0[2], v);
        v = fmaf(wv[3], r1[0], v); v = fmaf(wv[4], r1[1], v); v = fmaf(wv[5], r1[2], v);
        v = fmaf(wv[6], r2[0], v); v = fmaf(wv[7], r2[1], v); v = fmaf(wv[8], r2[2], v);
        float g = 0.5f * v * (1.f + erff(v * 0.70710678118654752440f));
        // conv2's SAME zero-pad: h1 at t=-1 / t=8192 must be exactly 0
        sh1[(s + 1) * SW + c] = ((unsigned)t < T_LEN) ? g : 0.f;
    }
    __syncthreads();

    // ---- phase D: conv2 + GELU + blend + ratio-mean over scales + write ----
    const float blend = 1.f / (1.f + expf(-blendl[0]));
    const float b2v = b2[ch];
    float wl[9];
    #pragma unroll
    for (int i = 0; i < 9; ++i) wl[i] = w2s[i];
    for (int c = 2 + tid; c < TTILE + 2; c += NTH) {
        float acc = 0.f;
        #pragma unroll 4
        for (int s = 1; s <= N_SC; ++s) {
            const float* r0 = sh1 + (s - 1) * SW + (c - 1);
            const float* r1 = r0 + SW;
            const float* r2 = r1 + SW;
            float v = b2v;
            v = fmaf(wl[0], r0[0], v); v = fmaf(wl[1], r0[1], v); v = fmaf(wl[2], r0[2], v);
            v = fmaf(wl[3], r1[0], v); v = fmaf(wl[4], r1[1], v); v = fmaf(wl[5], r1[2], v);
            v = fmaf(wl[6], r2[0], v); v = fmaf(wl[7], r2[1], v); v = fmaf(wl[8], r2[2], v);
            float h  = 0.5f * v * (1.f + erff(v * 0.70710678118654752440f));
            float cw = scw[s * SW + c];
            float bl = blend * h + (1.f - blend) * cw;
            acc += __fdividef(bl, cw + 1e-8f);
        }
        out[(size_t)row * T_LEN + (t0 + c - 2)] = sx[c + 256] * acc * (1.f / 16.f);
    }
}

extern "C" void kernel_launch(void* const* d_in, const int* in_sizes, int n_in,
                              void* d_out, int out_size)
{
    const float* x  = (const float*)d_in[0];
    const float* w1 = (const float*)d_in[1];
    const float* b1 = (const float*)d_in[2];
    const float* w2 = (const float*)d_in[3];
    const float* b2 = (const float*)d_in[4];
    const float* bl = (const float*)d_in[5];
    const float* ls = (const float*)d_in[6];
    float* out = (float*)d_out;

    const int rows = in_sizes[0] / T_LEN;   // B*C = 256

    const size_t smem = (size_t)(SXN + 2 * MAXW + 2 * 18 * SW + 144 + 12) * sizeof(float)
                        + 4 * 16 * sizeof(int);
    cudaFuncSetAttribute(wav_main_kernel, cudaFuncAttributeMaxDynamicSharedMemorySize, (int)smem);

    wav_init_kernel<<<1, 256>>>();
    dim3 grid(T_LEN / TTILE, rows);
    wav_main_kernel<<<grid, NTH, smem>>>(x, w1, b1, w2, b2, bl, ls, out);
}